// round 14
// baseline (speedup 1.0000x reference)
#include <cuda_runtime.h>
#include <cuda_fp16.h>
#include <math.h>
#include <stdint.h>

// Problem dims (fixed by the reference)
#define BB   16384
#define DD   1024
#define HALF 512
#define HID  4096

// ---------------------------------------------------------------------------
// Scratch (static device globals — no runtime allocation)
// ---------------------------------------------------------------------------
__device__ __half g_A [(size_t)BB * HALF];        // deinterleaved even channels (fp16)
__device__ __half g_H [(size_t)BB * 2 * HID];     // hidden acts [Hs | Ht] (fp16)
__device__ __half g_ST[(size_t)BB * DD];          // [s | t] per row (fp16)
__device__ __half g_W1[(size_t)2 * HID * HALF];   // K-major combined W1: [8192][512]
__device__ __half g_W2[(size_t)DD * HID];         // K-major combined W2: [1024][4096]

// ---------------------------------------------------------------------------
// Helpers
// ---------------------------------------------------------------------------
__device__ __forceinline__ uint32_t smem_u32(const void* p) {
    uint32_t a;
    asm("{ .reg .u64 t; cvta.to.shared.u64 t, %1; cvt.u32.u64 %0, t; }"
        : "=r"(a) : "l"(p));
    return a;
}
#define SWZ(x) ((x) ^ (((x) >> 3) & 0x70))

__device__ __forceinline__ void ldmx4(uint32_t& r0, uint32_t& r1,
                                      uint32_t& r2, uint32_t& r3, uint32_t addr) {
    asm volatile("ldmatrix.sync.aligned.m8n8.x4.shared.b16 {%0,%1,%2,%3}, [%4];"
                 : "=r"(r0), "=r"(r1), "=r"(r2), "=r"(r3) : "r"(addr));
}
__device__ __forceinline__ void mma_f16(float* c, const uint32_t* a, const uint32_t* b) {
    asm volatile(
        "mma.sync.aligned.m16n8k16.row.col.f32.f16.f16.f32 "
        "{%0,%1,%2,%3}, {%4,%5,%6,%7}, {%8,%9}, {%0,%1,%2,%3};"
        : "+f"(c[0]), "+f"(c[1]), "+f"(c[2]), "+f"(c[3])
        : "r"(a[0]), "r"(a[1]), "r"(a[2]), "r"(a[3]), "r"(b[0]), "r"(b[1]));
}

// ---------------------------------------------------------------------------
// 1) Fused prep: deinterleave a + 4 weight transposes, one launch.
// ---------------------------------------------------------------------------
__device__ __forceinline__ void do_transpose(__half* __restrict__ out,
                                             const float* __restrict__ in,
                                             int K, int N, int tb, int tid) {
    __shared__ float t[32][33];
    const int tilesX = N >> 5;
    const int bx = tb % tilesX, by = tb / tilesX;
    const int k0 = by * 32, n0 = bx * 32;
    const int x = tid & 31, y = tid >> 5;          // 32 x 8
#pragma unroll
    for (int dy = 0; dy < 32; dy += 8)
        t[y + dy][x] = in[(size_t)(k0 + y + dy) * N + n0 + x];
    __syncthreads();
#pragma unroll
    for (int dy = 0; dy < 32; dy += 8)
        out[(size_t)(n0 + y + dy) * K + k0 + x] = __float2half_rn(t[x][y + dy]);
}

__global__ void __launch_bounds__(256)
prep_kernel(const float* __restrict__ z,
            const float* __restrict__ W1s, const float* __restrict__ W1t,
            const float* __restrict__ W2s, const float* __restrict__ W2t)
{
    const int bid = blockIdx.x;
    const int tid = threadIdx.x;

    if (bid < 4096) {
        size_t base = ((size_t)bid * 256 + tid) * 8;      // output index into g_A
        const float4* zp = (const float4*)(z) + base / 2; // 2 outputs per float4
        __half h[8];
#pragma unroll
        for (int i = 0; i < 4; i++) {
            float4 v = zp[i];
            h[2 * i]     = __float2half_rn(v.x);
            h[2 * i + 1] = __float2half_rn(v.z);
        }
        *(uint4*)(g_A + base) = *(const uint4*)h;
        return;
    }
    const int bid2 = bid - 4096;
    const int which = bid2 >> 11;          // 0..3
    const int tb = bid2 & 2047;
    if (which == 0)      do_transpose(g_W1,                       W1s, HALF, HID, tb, tid);
    else if (which == 1) do_transpose(g_W1 + (size_t)HID * HALF,  W1t, HALF, HID, tb, tid);
    else if (which == 2) do_transpose(g_W2,                       W2s, HID, HALF, tb, tid);
    else                 do_transpose(g_W2 + (size_t)HALF * HID,  W2t, HID, HALF, tb, tid);
}

// ---------------------------------------------------------------------------
// 2) fp16 mma.sync GEMM (R7 config): C[m, n0g..] = act(A(branch) @ W^T + bias)
//    A: [M][K] row-major fp16. W: [Ntot][K] K-major fp16.
//    BM=128, BN=128, BK=64 (128B rows), 3-stage cp.async,
//    8 warps (2m x 4n), warp tile 64x32, mma m16n8k16, fp32 accum.
// ---------------------------------------------------------------------------
template <int RELU, typename OutT>
__global__ void __launch_bounds__(256, 2)
gemm_mma(const __half* __restrict__ A, int lda, int aOff,
         const __half* __restrict__ W,
         const float* __restrict__ bias0, const float* __restrict__ bias1, int Nb,
         OutT* __restrict__ C, int ldc, int K)
{
    constexpr int S = 3;
    constexpr int STAGE = 128 * 128;       // 16 KB per operand per stage

    extern __shared__ char smem[];
    uint32_t sb = smem_u32(smem);
    const uint32_t sA0 = sb;
    const uint32_t sB0 = sb + S * STAGE;

    const int tid = threadIdx.x;
    const int wid = tid >> 5, lid = tid & 31;
    const int warpM = wid & 1;             // 2 m-groups of 64
    const int warpN = wid >> 1;            // 4 n-groups of 32

    const int m0  = blockIdx.y * 128;
    const int n0g = blockIdx.x * 128;
    const int branch = (n0g >= Nb) ? 1 : 0;
    const __half* Ab = A + (size_t)m0 * lda + (branch ? aOff : 0);
    const __half* Wb = W + (size_t)n0g * K;
    const float* __restrict__ bias = branch ? bias1 : bias0;
    const int n0l = n0g - branch * Nb;

    // cp.async load map: 2 threads per 128B row, 4x16B each
    const int row = tid >> 1;
    const int cb  = (tid & 1) * 64;        // byte offset within 128B row
    const char* aRow = (const char*)(Ab + (size_t)row * lda) + cb;
    const char* wRow = (const char*)(Wb + (size_t)row * K)   + cb;
    const uint32_t rowb = row * 128 + cb;

    const int nK = K / 64;

#define LOAD_STAGE(st, chunk)                                                   \
    do {                                                                        \
        uint32_t abase_ = sA0 + (st) * STAGE;                                   \
        uint32_t bbase_ = sB0 + (st) * STAGE;                                   \
        const char* ag_ = aRow + (size_t)(chunk) * 128;  /* 64 fp16 = 128B */   \
        const char* wg_ = wRow + (size_t)(chunk) * 128;                         \
        _Pragma("unroll")                                                       \
        for (int i_ = 0; i_ < 4; i_++) {                                        \
            uint32_t o_ = rowb + i_ * 16;                                       \
            asm volatile("cp.async.cg.shared.global [%0], [%1], 16;"            \
                         :: "r"(abase_ + SWZ(o_)), "l"(ag_ + i_ * 16));         \
        }                                                                       \
        _Pragma("unroll")                                                       \
        for (int i_ = 0; i_ < 4; i_++) {                                        \
            uint32_t o_ = rowb + i_ * 16;                                       \
            asm volatile("cp.async.cg.shared.global [%0], [%1], 16;"            \
                         :: "r"(bbase_ + SWZ(o_)), "l"(wg_ + i_ * 16));         \
        }                                                                       \
    } while (0)

    // ldmatrix lane address components (xor pattern is lane-constant)
    const int laneRowA  = (lid & 7) + ((lid >> 3) & 1) * 8;
    const int colHalfA  = (lid >> 4) & 1;
    const uint32_t xorA = (uint32_t)((laneRowA & 7) * 16);
    const uint32_t aRowOff = (uint32_t)((warpM * 64 + laneRowA) * 128);

    const int laneRowB  = lid & 7;
    const int mIdxB     = lid >> 3;
    const int ntOffB    = (mIdxB >> 1) * 8;
    const int colHalfB  = mIdxB & 1;
    const uint32_t xorB = (uint32_t)((laneRowB & 7) * 16);
    const uint32_t bRowOff = (uint32_t)((warpN * 32 + ntOffB + laneRowB) * 128);

    float acc[4][4][4];
#pragma unroll
    for (int i = 0; i < 4; i++)
#pragma unroll
        for (int j = 0; j < 4; j++)
#pragma unroll
            for (int k = 0; k < 4; k++) acc[i][j][k] = 0.0f;

    // Prologue: stages 0,1
    LOAD_STAGE(0, 0);
    asm volatile("cp.async.commit_group;" ::: "memory");
    LOAD_STAGE(1, 1);
    asm volatile("cp.async.commit_group;" ::: "memory");

    for (int it = 0; it < nK; it++) {
        asm volatile("cp.async.wait_group 1;" ::: "memory");
        __syncthreads();

        if (it + 2 < nK) LOAD_STAGE((it + 2) % S, it + 2);
        asm volatile("cp.async.commit_group;" ::: "memory");

        const int st = it % S;
        const uint32_t sAst = sA0 + st * STAGE;
        const uint32_t sBst = sB0 + st * STAGE;

        // 4 k-chunks of 32B (16 fp16) per 128B row
#pragma unroll
        for (int ks = 0; ks < 4; ks++) {
            const uint32_t kb = (uint32_t)(ks * 32);
            uint32_t a[4][4];
#pragma unroll
            for (int mt = 0; mt < 4; mt++)
                ldmx4(a[mt][0], a[mt][1], a[mt][2], a[mt][3],
                      sAst + aRowOff + mt * 16 * 128 + ((kb + colHalfA * 16) ^ xorA));
            uint32_t b[4][2];
#pragma unroll
            for (int ntp = 0; ntp < 2; ntp++) {
                uint32_t r0, r1, r2, r3;
                ldmx4(r0, r1, r2, r3,
                      sBst + bRowOff + ntp * 16 * 128 + ((kb + colHalfB * 16) ^ xorB));
                b[2 * ntp][0] = r0; b[2 * ntp][1] = r1;
                b[2 * ntp + 1][0] = r2; b[2 * ntp + 1][1] = r3;
            }
#pragma unroll
            for (int mt = 0; mt < 4; mt++)
#pragma unroll
                for (int nt = 0; nt < 4; nt++)
                    mma_f16(acc[mt][nt], a[mt], b[nt]);
        }
    }

    // Epilogue: bias (+ReLU) and store (fp16 for both H and ST)
    const int lrow = lid >> 2;
    const int lcol = (lid & 3) * 2;
    float2 bv[4];
#pragma unroll
    for (int nt = 0; nt < 4; nt++)
        bv[nt] = *(const float2*)(bias + n0l + warpN * 32 + nt * 8 + lcol);

#pragma unroll
    for (int nt = 0; nt < 4; nt++) {
        const int cl = warpN * 32 + nt * 8 + lcol;
#pragma unroll
        for (int mt = 0; mt < 4; mt++) {
            const int r = m0 + warpM * 64 + mt * 16 + lrow;
            float v00 = acc[mt][nt][0] + bv[nt].x, v01 = acc[mt][nt][1] + bv[nt].y;
            float v10 = acc[mt][nt][2] + bv[nt].x, v11 = acc[mt][nt][3] + bv[nt].y;
            if (RELU) {
                v00 = fmaxf(v00, 0.0f); v01 = fmaxf(v01, 0.0f);
                v10 = fmaxf(v10, 0.0f); v11 = fmaxf(v11, 0.0f);
            }
            OutT* c0 = C + (size_t)r * ldc + n0g + cl;
            OutT* c1 = C + (size_t)(r + 8) * ldc + n0g + cl;
            if (sizeof(OutT) == 2) {
                *(__half2*)c0 = __floats2half2_rn(v00, v01);
                *(__half2*)c1 = __floats2half2_rn(v10, v11);
            } else {
                *(float2*)c0 = make_float2(v00, v01);
                *(float2*)c1 = make_float2(v10, v11);
            }
        }
    }
#undef LOAD_STAGE
}

// ---------------------------------------------------------------------------
// 3) Finalize: b_out = b*exp(s)+t, interleave, logdet = sum(s).
//    4 rows per block (grid BB/4) for higher per-thread MLP; per-row math
//    identical to the R13 version.
// ---------------------------------------------------------------------------
__global__ void __launch_bounds__(256)
finalize_kernel(const float* __restrict__ z,
                float* __restrict__ zout, float* __restrict__ logdet)
{
    const int row0 = blockIdx.x * 4;
    const int tid  = threadIdx.x;
    __shared__ float wsum[4][8];

    float lsum[4];
#pragma unroll
    for (int rr = 0; rr < 4; rr++) {
        const int row = row0 + rr;
        const float4* zr = (const float4*)(z    + (size_t)row * DD);
        float4*       zo = (float4*)      (zout + (size_t)row * DD);
        const __half* st = g_ST + (size_t)row * DD;

        float4 v  = zr[tid];                                       // a0 b0 a1 b1
        float2 sv = __half22float2(*(const __half2*)(st + 2 * tid));        // s0 s1
        float2 tv = __half22float2(*(const __half2*)(st + HALF + 2 * tid)); // t0 t1

        lsum[rr] = sv.x + sv.y;
        v.y = fmaf(v.y, __expf(sv.x), tv.x);
        v.w = fmaf(v.w, __expf(sv.y), tv.y);
        zo[tid] = v;
    }

#pragma unroll
    for (int rr = 0; rr < 4; rr++)
#pragma unroll
        for (int off = 16; off > 0; off >>= 1)
            lsum[rr] += __shfl_xor_sync(0xffffffffu, lsum[rr], off);
    if ((tid & 31) == 0) {
#pragma unroll
        for (int rr = 0; rr < 4; rr++)
            wsum[rr][tid >> 5] = lsum[rr];
    }
    __syncthreads();
    if (tid < 32) {
        const int rr = tid >> 3;
        float w = wsum[rr][tid & 7];
#pragma unroll
        for (int off = 4; off > 0; off >>= 1)
            w += __shfl_xor_sync(0xffffffffu, w, off, 8);
        if ((tid & 7) == 0) logdet[row0 + rr] = w;
    }
}

// ---------------------------------------------------------------------------
// Launch
// ---------------------------------------------------------------------------
extern "C" void kernel_launch(void* const* d_in, const int* in_sizes, int n_in,
                              void* d_out, int out_size)
{
    const float* z   = (const float*)d_in[0];
    const float* W1s = (const float*)d_in[1];
    const float* b1s = (const float*)d_in[2];
    const float* W2s = (const float*)d_in[3];
    const float* b2s = (const float*)d_in[4];
    const float* W1t = (const float*)d_in[5];
    const float* b1t = (const float*)d_in[6];
    const float* W2t = (const float*)d_in[7];
    const float* b2t = (const float*)d_in[8];

    float* out    = (float*)d_out;
    float* zout   = out;
    float* logdet = out + (size_t)BB * DD;

    __half *pA, *pH, *pW1, *pW2, *pST;
    cudaGetSymbolAddress((void**)&pA,  g_A);
    cudaGetSymbolAddress((void**)&pH,  g_H);
    cudaGetSymbolAddress((void**)&pST, g_ST);
    cudaGetSymbolAddress((void**)&pW1, g_W1);
    cudaGetSymbolAddress((void**)&pW2, g_W2);

    const int SMEMSZ = 6 * 16384;   // 98304 B (3 stages x (A+B) x 16KB)
    static bool attr_set = false;
    if (!attr_set) {
        cudaFuncSetAttribute((const void*)gemm_mma<1, __half>,
                             cudaFuncAttributeMaxDynamicSharedMemorySize, SMEMSZ);
        cudaFuncSetAttribute((const void*)gemm_mma<0, __half>,
                             cudaFuncAttributeMaxDynamicSharedMemorySize, SMEMSZ);
        attr_set = true;
    }

    // 1) fused prep: deinterleave + all 4 weight transposes
    prep_kernel<<<12288, 256>>>(z, W1s, W1t, W2s, W2t);

    // 2) H[B, 8192] = relu(a @ [W1s|W1t] + bias)  (fp16 output)
    {
        dim3 grid(2 * HID / 128, BB / 128);      // (64, 128)
        gemm_mma<1, __half><<<grid, 256, SMEMSZ>>>(pA, HALF, 0, pW1,
                                                   b1s, b1t, HID, pH, 2 * HID, HALF);
    }

    // 3) [s|t][B, 1024] = H(branch half) @ W2 + bias  (fp16 output)
    {
        dim3 grid(DD / 128, BB / 128);           // (8, 128)
        gemm_mma<0, __half><<<grid, 256, SMEMSZ>>>(pH, 2 * HID, HID, pW2,
                                                   b2s, b2t, HALF, pST, DD, HID);
    }

    // 4) finalize: coupling + logdet (4 rows per block)
    finalize_kernel<<<BB / 4, 256>>>(z, zout, logdet);
}

// round 15
// speedup vs baseline: 1.0033x; 1.0033x over previous
#include <cuda_runtime.h>
#include <cuda_fp16.h>
#include <math.h>
#include <stdint.h>

// Problem dims (fixed by the reference)
#define BB   16384
#define DD   1024
#define HALF 512
#define HID  4096

// ---------------------------------------------------------------------------
// Scratch (static device globals — no runtime allocation)
// ---------------------------------------------------------------------------
__device__ __half g_A [(size_t)BB * HALF];        // deinterleaved even channels (fp16)
__device__ __half g_H [(size_t)BB * 2 * HID];     // hidden acts [Hs | Ht] (fp16)
__device__ __half g_ST[(size_t)BB * DD];          // [s | t] per row (fp16)
__device__ __half g_W1[(size_t)2 * HID * HALF];   // K-major combined W1: [8192][512]
__device__ __half g_W2[(size_t)DD * HID];         // K-major combined W2: [1024][4096]

// ---------------------------------------------------------------------------
// Helpers
// ---------------------------------------------------------------------------
__device__ __forceinline__ uint32_t smem_u32(const void* p) {
    uint32_t a;
    asm("{ .reg .u64 t; cvta.to.shared.u64 t, %1; cvt.u32.u64 %0, t; }"
        : "=r"(a) : "l"(p));
    return a;
}
#define SWZ(x) ((x) ^ (((x) >> 3) & 0x70))

__device__ __forceinline__ void ldmx4(uint32_t& r0, uint32_t& r1,
                                      uint32_t& r2, uint32_t& r3, uint32_t addr) {
    asm volatile("ldmatrix.sync.aligned.m8n8.x4.shared.b16 {%0,%1,%2,%3}, [%4];"
                 : "=r"(r0), "=r"(r1), "=r"(r2), "=r"(r3) : "r"(addr));
}
__device__ __forceinline__ void mma_f16(float* c, const uint32_t* a, const uint32_t* b) {
    asm volatile(
        "mma.sync.aligned.m16n8k16.row.col.f32.f16.f16.f32 "
        "{%0,%1,%2,%3}, {%4,%5,%6,%7}, {%8,%9}, {%0,%1,%2,%3};"
        : "+f"(c[0]), "+f"(c[1]), "+f"(c[2]), "+f"(c[3])
        : "r"(a[0]), "r"(a[1]), "r"(a[2]), "r"(a[3]), "r"(b[0]), "r"(b[1]));
}

// Streaming float4 load (.nc) / store (.cs)
__device__ __forceinline__ float4 ldg_nc_f4(const float4* p) {
    float4 v;
    asm volatile("ld.global.nc.v4.f32 {%0,%1,%2,%3}, [%4];"
                 : "=f"(v.x), "=f"(v.y), "=f"(v.z), "=f"(v.w) : "l"(p));
    return v;
}
__device__ __forceinline__ void stg_cs_f4(float4* p, float4 v) {
    asm volatile("st.global.cs.v4.f32 [%0], {%1,%2,%3,%4};"
                 :: "l"(p), "f"(v.x), "f"(v.y), "f"(v.z), "f"(v.w));
}

// ---------------------------------------------------------------------------
// 1) Fused prep: deinterleave a + 4 weight transposes, one launch.
// ---------------------------------------------------------------------------
__device__ __forceinline__ void do_transpose(__half* __restrict__ out,
                                             const float* __restrict__ in,
                                             int K, int N, int tb, int tid) {
    __shared__ float t[32][33];
    const int tilesX = N >> 5;
    const int bx = tb % tilesX, by = tb / tilesX;
    const int k0 = by * 32, n0 = bx * 32;
    const int x = tid & 31, y = tid >> 5;          // 32 x 8
#pragma unroll
    for (int dy = 0; dy < 32; dy += 8)
        t[y + dy][x] = in[(size_t)(k0 + y + dy) * N + n0 + x];
    __syncthreads();
#pragma unroll
    for (int dy = 0; dy < 32; dy += 8)
        out[(size_t)(n0 + y + dy) * K + k0 + x] = __float2half_rn(t[x][y + dy]);
}

__global__ void __launch_bounds__(256)
prep_kernel(const float* __restrict__ z,
            const float* __restrict__ W1s, const float* __restrict__ W1t,
            const float* __restrict__ W2s, const float* __restrict__ W2t)
{
    const int bid = blockIdx.x;
    const int tid = threadIdx.x;

    if (bid < 4096) {
        size_t base = ((size_t)bid * 256 + tid) * 8;      // output index into g_A
        const float4* zp = (const float4*)(z) + base / 2; // 2 outputs per float4
        __half h[8];
#pragma unroll
        for (int i = 0; i < 4; i++) {
            float4 v = zp[i];
            h[2 * i]     = __float2half_rn(v.x);
            h[2 * i + 1] = __float2half_rn(v.z);
        }
        *(uint4*)(g_A + base) = *(const uint4*)h;
        return;
    }
    const int bid2 = bid - 4096;
    const int which = bid2 >> 11;          // 0..3
    const int tb = bid2 & 2047;
    if (which == 0)      do_transpose(g_W1,                       W1s, HALF, HID, tb, tid);
    else if (which == 1) do_transpose(g_W1 + (size_t)HID * HALF,  W1t, HALF, HID, tb, tid);
    else if (which == 2) do_transpose(g_W2,                       W2s, HID, HALF, tb, tid);
    else                 do_transpose(g_W2 + (size_t)HALF * HID,  W2t, HID, HALF, tb, tid);
}

// ---------------------------------------------------------------------------
// 2) fp16 mma.sync GEMM (R7 config): C[m, n0g..] = act(A(branch) @ W^T + bias)
//    A: [M][K] row-major fp16. W: [Ntot][K] K-major fp16.
//    BM=128, BN=128, BK=64 (128B rows), 3-stage cp.async,
//    8 warps (2m x 4n), warp tile 64x32, mma m16n8k16, fp32 accum.
// ---------------------------------------------------------------------------
template <int RELU, typename OutT>
__global__ void __launch_bounds__(256, 2)
gemm_mma(const __half* __restrict__ A, int lda, int aOff,
         const __half* __restrict__ W,
         const float* __restrict__ bias0, const float* __restrict__ bias1, int Nb,
         OutT* __restrict__ C, int ldc, int K)
{
    constexpr int S = 3;
    constexpr int STAGE = 128 * 128;       // 16 KB per operand per stage

    extern __shared__ char smem[];
    uint32_t sb = smem_u32(smem);
    const uint32_t sA0 = sb;
    const uint32_t sB0 = sb + S * STAGE;

    const int tid = threadIdx.x;
    const int wid = tid >> 5, lid = tid & 31;
    const int warpM = wid & 1;             // 2 m-groups of 64
    const int warpN = wid >> 1;            // 4 n-groups of 32

    const int m0  = blockIdx.y * 128;
    const int n0g = blockIdx.x * 128;
    const int branch = (n0g >= Nb) ? 1 : 0;
    const __half* Ab = A + (size_t)m0 * lda + (branch ? aOff : 0);
    const __half* Wb = W + (size_t)n0g * K;
    const float* __restrict__ bias = branch ? bias1 : bias0;
    const int n0l = n0g - branch * Nb;

    // cp.async load map: 2 threads per 128B row, 4x16B each
    const int row = tid >> 1;
    const int cb  = (tid & 1) * 64;        // byte offset within 128B row
    const char* aRow = (const char*)(Ab + (size_t)row * lda) + cb;
    const char* wRow = (const char*)(Wb + (size_t)row * K)   + cb;
    const uint32_t rowb = row * 128 + cb;

    const int nK = K / 64;

#define LOAD_STAGE(st, chunk)                                                   \
    do {                                                                        \
        uint32_t abase_ = sA0 + (st) * STAGE;                                   \
        uint32_t bbase_ = sB0 + (st) * STAGE;                                   \
        const char* ag_ = aRow + (size_t)(chunk) * 128;  /* 64 fp16 = 128B */   \
        const char* wg_ = wRow + (size_t)(chunk) * 128;                         \
        _Pragma("unroll")                                                       \
        for (int i_ = 0; i_ < 4; i_++) {                                        \
            uint32_t o_ = rowb + i_ * 16;                                       \
            asm volatile("cp.async.cg.shared.global [%0], [%1], 16;"            \
                         :: "r"(abase_ + SWZ(o_)), "l"(ag_ + i_ * 16));         \
        }                                                                       \
        _Pragma("unroll")                                                       \
        for (int i_ = 0; i_ < 4; i_++) {                                        \
            uint32_t o_ = rowb + i_ * 16;                                       \
            asm volatile("cp.async.cg.shared.global [%0], [%1], 16;"            \
                         :: "r"(bbase_ + SWZ(o_)), "l"(wg_ + i_ * 16));         \
        }                                                                       \
    } while (0)

    // ldmatrix lane address components (xor pattern is lane-constant)
    const int laneRowA  = (lid & 7) + ((lid >> 3) & 1) * 8;
    const int colHalfA  = (lid >> 4) & 1;
    const uint32_t xorA = (uint32_t)((laneRowA & 7) * 16);
    const uint32_t aRowOff = (uint32_t)((warpM * 64 + laneRowA) * 128);

    const int laneRowB  = lid & 7;
    const int mIdxB     = lid >> 3;
    const int ntOffB    = (mIdxB >> 1) * 8;
    const int colHalfB  = mIdxB & 1;
    const uint32_t xorB = (uint32_t)((laneRowB & 7) * 16);
    const uint32_t bRowOff = (uint32_t)((warpN * 32 + ntOffB + laneRowB) * 128);

    float acc[4][4][4];
#pragma unroll
    for (int i = 0; i < 4; i++)
#pragma unroll
        for (int j = 0; j < 4; j++)
#pragma unroll
            for (int k = 0; k < 4; k++) acc[i][j][k] = 0.0f;

    // Prologue: stages 0,1
    LOAD_STAGE(0, 0);
    asm volatile("cp.async.commit_group;" ::: "memory");
    LOAD_STAGE(1, 1);
    asm volatile("cp.async.commit_group;" ::: "memory");

    for (int it = 0; it < nK; it++) {
        asm volatile("cp.async.wait_group 1;" ::: "memory");
        __syncthreads();

        if (it + 2 < nK) LOAD_STAGE((it + 2) % S, it + 2);
        asm volatile("cp.async.commit_group;" ::: "memory");

        const int st = it % S;
        const uint32_t sAst = sA0 + st * STAGE;
        const uint32_t sBst = sB0 + st * STAGE;

        // 4 k-chunks of 32B (16 fp16) per 128B row
#pragma unroll
        for (int ks = 0; ks < 4; ks++) {
            const uint32_t kb = (uint32_t)(ks * 32);
            uint32_t a[4][4];
#pragma unroll
            for (int mt = 0; mt < 4; mt++)
                ldmx4(a[mt][0], a[mt][1], a[mt][2], a[mt][3],
                      sAst + aRowOff + mt * 16 * 128 + ((kb + colHalfA * 16) ^ xorA));
            uint32_t b[4][2];
#pragma unroll
            for (int ntp = 0; ntp < 2; ntp++) {
                uint32_t r0, r1, r2, r3;
                ldmx4(r0, r1, r2, r3,
                      sBst + bRowOff + ntp * 16 * 128 + ((kb + colHalfB * 16) ^ xorB));
                b[2 * ntp][0] = r0; b[2 * ntp][1] = r1;
                b[2 * ntp + 1][0] = r2; b[2 * ntp + 1][1] = r3;
            }
#pragma unroll
            for (int mt = 0; mt < 4; mt++)
#pragma unroll
                for (int nt = 0; nt < 4; nt++)
                    mma_f16(acc[mt][nt], a[mt], b[nt]);
        }
    }

    // Epilogue: bias (+ReLU) and store (fp16 for both H and ST)
    const int lrow = lid >> 2;
    const int lcol = (lid & 3) * 2;
    float2 bv[4];
#pragma unroll
    for (int nt = 0; nt < 4; nt++)
        bv[nt] = *(const float2*)(bias + n0l + warpN * 32 + nt * 8 + lcol);

#pragma unroll
    for (int nt = 0; nt < 4; nt++) {
        const int cl = warpN * 32 + nt * 8 + lcol;
#pragma unroll
        for (int mt = 0; mt < 4; mt++) {
            const int r = m0 + warpM * 64 + mt * 16 + lrow;
            float v00 = acc[mt][nt][0] + bv[nt].x, v01 = acc[mt][nt][1] + bv[nt].y;
            float v10 = acc[mt][nt][2] + bv[nt].x, v11 = acc[mt][nt][3] + bv[nt].y;
            if (RELU) {
                v00 = fmaxf(v00, 0.0f); v01 = fmaxf(v01, 0.0f);
                v10 = fmaxf(v10, 0.0f); v11 = fmaxf(v11, 0.0f);
            }
            OutT* c0 = C + (size_t)r * ldc + n0g + cl;
            OutT* c1 = C + (size_t)(r + 8) * ldc + n0g + cl;
            if (sizeof(OutT) == 2) {
                *(__half2*)c0 = __floats2half2_rn(v00, v01);
                *(__half2*)c1 = __floats2half2_rn(v10, v11);
            } else {
                *(float2*)c0 = make_float2(v00, v01);
                *(float2*)c1 = make_float2(v10, v11);
            }
        }
    }
#undef LOAD_STAGE
}

// ---------------------------------------------------------------------------
// 3) Finalize: b_out = b*exp(s)+t, interleave, logdet = sum(s).
//    2 rows per block (measured-best config); z via ld.global.nc,
//    zout via st.global.cs (streaming — never re-read).
// ---------------------------------------------------------------------------
__global__ void __launch_bounds__(256)
finalize_kernel(const float* __restrict__ z,
                float* __restrict__ zout, float* __restrict__ logdet)
{
    const int row0 = blockIdx.x * 2;
    const int tid  = threadIdx.x;
    __shared__ float wsum[2][8];

    float lsum[2];
#pragma unroll
    for (int rr = 0; rr < 2; rr++) {
        const int row = row0 + rr;
        const float4* zr = (const float4*)(z    + (size_t)row * DD);
        float4*       zo = (float4*)      (zout + (size_t)row * DD);
        const __half* st = g_ST + (size_t)row * DD;

        float4 v  = ldg_nc_f4(zr + tid);                           // a0 b0 a1 b1
        float2 sv = __half22float2(*(const __half2*)(st + 2 * tid));        // s0 s1
        float2 tv = __half22float2(*(const __half2*)(st + HALF + 2 * tid)); // t0 t1

        lsum[rr] = sv.x + sv.y;
        v.y = fmaf(v.y, __expf(sv.x), tv.x);
        v.w = fmaf(v.w, __expf(sv.y), tv.y);
        stg_cs_f4(zo + tid, v);
    }

#pragma unroll
    for (int rr = 0; rr < 2; rr++)
#pragma unroll
        for (int off = 16; off > 0; off >>= 1)
            lsum[rr] += __shfl_xor_sync(0xffffffffu, lsum[rr], off);
    if ((tid & 31) == 0) {
        wsum[0][tid >> 5] = lsum[0];
        wsum[1][tid >> 5] = lsum[1];
    }
    __syncthreads();
    if (tid < 16) {
        const int rr = tid >> 3;
        float w = wsum[rr][tid & 7];
#pragma unroll
        for (int off = 4; off > 0; off >>= 1)
            w += __shfl_xor_sync(0x0000ffffu, w, off, 8);
        if ((tid & 7) == 0) logdet[row0 + rr] = w;
    }
}

// ---------------------------------------------------------------------------
// Launch
// ---------------------------------------------------------------------------
extern "C" void kernel_launch(void* const* d_in, const int* in_sizes, int n_in,
                              void* d_out, int out_size)
{
    const float* z   = (const float*)d_in[0];
    const float* W1s = (const float*)d_in[1];
    const float* b1s = (const float*)d_in[2];
    const float* W2s = (const float*)d_in[3];
    const float* b2s = (const float*)d_in[4];
    const float* W1t = (const float*)d_in[5];
    const float* b1t = (const float*)d_in[6];
    const float* W2t = (const float*)d_in[7];
    const float* b2t = (const float*)d_in[8];

    float* out    = (float*)d_out;
    float* zout   = out;
    float* logdet = out + (size_t)BB * DD;

    __half *pA, *pH, *pW1, *pW2, *pST;
    cudaGetSymbolAddress((void**)&pA,  g_A);
    cudaGetSymbolAddress((void**)&pH,  g_H);
    cudaGetSymbolAddress((void**)&pST, g_ST);
    cudaGetSymbolAddress((void**)&pW1, g_W1);
    cudaGetSymbolAddress((void**)&pW2, g_W2);

    const int SMEMSZ = 6 * 16384;   // 98304 B (3 stages x (A+B) x 16KB)
    static bool attr_set = false;
    if (!attr_set) {
        cudaFuncSetAttribute((const void*)gemm_mma<1, __half>,
                             cudaFuncAttributeMaxDynamicSharedMemorySize, SMEMSZ);
        cudaFuncSetAttribute((const void*)gemm_mma<0, __half>,
                             cudaFuncAttributeMaxDynamicSharedMemorySize, SMEMSZ);
        attr_set = true;
    }

    // 1) fused prep: deinterleave + all 4 weight transposes
    prep_kernel<<<12288, 256>>>(z, W1s, W1t, W2s, W2t);

    // 2) H[B, 8192] = relu(a @ [W1s|W1t] + bias)  (fp16 output)
    {
        dim3 grid(2 * HID / 128, BB / 128);      // (64, 128)
        gemm_mma<1, __half><<<grid, 256, SMEMSZ>>>(pA, HALF, 0, pW1,
                                                   b1s, b1t, HID, pH, 2 * HID, HALF);
    }

    // 3) [s|t][B, 1024] = H(branch half) @ W2 + bias  (fp16 output)
    {
        dim3 grid(DD / 128, BB / 128);           // (8, 128)
        gemm_mma<0, __half><<<grid, 256, SMEMSZ>>>(pH, 2 * HID, HID, pW2,
                                                   b2s, b2t, HALF, pST, DD, HID);
    }

    // 4) finalize: coupling + logdet (2 rows per block)
    finalize_kernel<<<BB / 2, 256>>>(z, zout, logdet);
}